// round 5
// baseline (speedup 1.0000x reference)
#include <cuda_runtime.h>
#include <math.h>

// Problem constants (fixed by the dataset)
#define L_DIM 16384
#define H_DIM 1024

// Tiling: each block handles CHUNK rows x 128 channels, 1 channel/thread.
// Scalar (vs float2) lets us double GROUPS so CHUNK can grow 64->128
// (halo amplification 2.0x -> 1.5x, -32MB L2 traffic) at UNCHANGED
// occupancy: grid = 128 x 8 = 1024 blocks = 4096 warps (~28/SM).
// Round-4 evidence says we sit on the LTS throughput cap (~9.1 TB/s of L2
// traffic), so bytes, not warps, are the lever.
#define CHUNK  128
#define GROUPS 8          // H / TPB
#define TPB    128
#define BATCH  16         // outstanding LDG.32 per thread per buffer

__device__ __forceinline__ void loadB(float v[BATCH], const float* px, int off) {
#pragma unroll
    for (int j = 0; j < BATCH; ++j)
        v[j] = px[off + j * H_DIM];     // BATCH back-to-back LDG.32 (coalesced)
}

__device__ __forceinline__ void procB(const float v[BATCH], float A, float& acc,
                                      float* po, int off, bool store) {
#pragma unroll
    for (int j = 0; j < BATCH; ++j) {
        acc = fmaf(A, acc, v[j]);
        if (store)   // evict-first store: don't let out[] evict x[] halo lines from L2
            __stcs(po + off + j * H_DIM, acc);
    }
}

// 8 blocks/SM (1024 threads) -> 64-reg/thread budget; buffers take 32.
__global__ __launch_bounds__(TPB, 8)
void LI_scan_kernel(const float* __restrict__ x,
                    const float* __restrict__ tau,
                    float* __restrict__ out) {
    const int chunk_start = blockIdx.x * CHUNK;
    const int ch          = blockIdx.y * TPB + threadIdx.x;

    // Per-channel decay A = exp(tau)
    const float A = expf(tau[ch]);

    // Runtime halo length K: smallest K with A^K < 1e-6 (output is O(1),
    // test tolerance is 1e-3 -> 3 orders of margin). Rounded up to a BATCH
    // multiple so every batch is full. Falls back to exact full prefix if A~1.
    int K;
    if (!(A < 0.999999f)) {
        K = chunk_start;                       // no usable decay: exact prefix
    } else if (A <= 1e-12f) {
        K = 0;
    } else {
        float kf = logf(1e-6f) / logf(A);      // both logs negative -> positive
        int   ki = (int)ceilf(kf);
        if (ki < 0) ki = 0;
        ki = (ki + BATCH - 1) & ~(BATCH - 1);  // round up to multiple of BATCH
        K = ki < chunk_start ? ki : chunk_start;  // chunk_start % BATCH == 0
    }

    // Block-uniform K (keeps batch loop structure aligned across the block)
    __shared__ int sK;
    if (threadIdx.x == 0) sK = 0;
    __syncthreads();
    atomicMax(&sK, K);
    __syncthreads();
    K = sK;

    const float* px = x + ch;
    float*       po = out + ch;

    float acc = 0.f;

    // ---- Fused halo + main loop, software-pipelined (double buffer) ----
    // Rows [chunk_start-K, chunk_start) warm up acc (no stores);
    // rows [chunk_start, chunk_start+CHUNK) also store. K and CHUNK are both
    // multiples of BATCH, so each batch is uniformly halo or main.
    // 32-bit element offsets: L*H = 2^24 fits comfortably.
    int off        = (chunk_start - K) * H_DIM;  // current batch offset
    const int off0 = chunk_start * H_DIM;        // first storing offset
    const int nb   = (K + CHUNK) / BATCH;        // >= CHUNK/BATCH = 8

    float v0[BATCH], v1[BATCH];
    loadB(v0, px, off);
    int b = 0;
    while (true) {
        if (b + 1 < nb) loadB(v1, px, off + BATCH * H_DIM);  // prefetch next batch
        procB(v0, A, acc, po, off, off >= off0);
        off += BATCH * H_DIM; if (++b >= nb) break;
        if (b + 1 < nb) loadB(v0, px, off + BATCH * H_DIM);  // prefetch next batch
        procB(v1, A, acc, po, off, off >= off0);
        off += BATCH * H_DIM; if (++b >= nb) break;
    }
}

extern "C" void kernel_launch(void* const* d_in, const int* in_sizes, int n_in,
                              void* d_out, int out_size) {
    const float* x   = (const float*)d_in[0];   // (L, H) fp32
    const float* tau = (const float*)d_in[1];   // (H,)   fp32
    float*       out = (float*)d_out;           // (L, H) fp32

    dim3 grid(L_DIM / CHUNK, GROUPS);
    LI_scan_kernel<<<grid, TPB>>>(x, tau, out);
}